// round 8
// baseline (speedup 1.0000x reference)
#include <cuda_runtime.h>

#define BB 8
#define NN 2048
#define FF 128

// Scratch (no allocation allowed in kernel_launch)
__device__ float g_Wh[BB * NN * FF];   // 32 MB
__device__ float g_s1[BB * NN];
__device__ float g_s2[BB * NN];

// ---------- packed f32x2 helpers (FFMA2 — PTX-only on sm_103a) ----------
__device__ __forceinline__ unsigned long long pack2(float x, float y) {
    unsigned long long r;
    asm("mov.b64 %0, {%1, %2};" : "=l"(r) : "f"(x), "f"(y));
    return r;
}
__device__ __forceinline__ void unpack2(unsigned long long v, float& x, float& y) {
    asm("mov.b64 {%0, %1}, %2;" : "=f"(x), "=f"(y) : "l"(v));
}
__device__ __forceinline__ unsigned long long ffma2(unsigned long long a,
                                                    unsigned long long b,
                                                    unsigned long long c) {
    unsigned long long d;
    asm("fma.rn.f32x2 %0, %1, %2, %3;" : "=l"(d) : "l"(a), "l"(b), "l"(c));
    return d;
}

// =====================================================================
// Kernel 1: Wh = h @ W.   Block: 256 threads, 32 rows, K-tiled by 32.
// thread owns 4 f (float4 of W) x 4 rows -> 16 accumulators as 8 f32x2.
// =====================================================================
__global__ void __launch_bounds__(256) gat_wh(const float* __restrict__ h,
                                              const float* __restrict__ W) {
    const int row0 = blockIdx.x * 32;
    const int tid  = threadIdx.x;
    const int fgrp = tid & 31;   // f = fgrp*4 .. +3
    const int rgrp = tid >> 5;   // r = rgrp*4 .. +3

    __shared__ __align__(16) float W_sm[32 * 128];
    __shared__ float h_sm[32 * 32];

    unsigned long long acc[4][2];
#pragma unroll
    for (int r = 0; r < 4; ++r) { acc[r][0] = 0ull; acc[r][1] = 0ull; }

    for (int kt = 0; kt < 128; kt += 32) {
        __syncthreads();
        // W tile [32 k][128 f] — coalesced float4
        const float4* wsrc = reinterpret_cast<const float4*>(W + kt * 128);
        float4* wdst = reinterpret_cast<float4*>(W_sm);
#pragma unroll
        for (int v = 0; v < 4; ++v) wdst[tid + v * 256] = wsrc[tid + v * 256];
        // h tile [32 rows][32 k]
#pragma unroll
        for (int v = 0; v < 4; ++v) {
            int idx = tid + v * 256;
            int r = idx >> 5, kk = idx & 31;
            h_sm[idx] = h[(size_t)(row0 + r) * 128 + kt + kk];
        }
        __syncthreads();
#pragma unroll
        for (int kk = 0; kk < 32; ++kk) {
            ulonglong2 wq = *reinterpret_cast<const ulonglong2*>(&W_sm[kk * 128 + fgrp * 4]);
#pragma unroll
            for (int r = 0; r < 4; ++r) {
                float hv = h_sm[(rgrp * 4 + r) * 32 + kk];  // warp broadcast
                unsigned long long h2 = pack2(hv, hv);
                acc[r][0] = ffma2(h2, wq.x, acc[r][0]);
                acc[r][1] = ffma2(h2, wq.y, acc[r][1]);
            }
        }
    }
#pragma unroll
    for (int r = 0; r < 4; ++r) {
        float x0, x1, x2, x3;
        unpack2(acc[r][0], x0, x1);
        unpack2(acc[r][1], x2, x3);
        *reinterpret_cast<float4*>(&g_Wh[(size_t)(row0 + rgrp * 4 + r) * 128 + fgrp * 4]) =
            make_float4(x0, x1, x2, x3);
    }
}

// =====================================================================
// Kernel 2: s1 = Wh @ a1, s2 = Wh @ a2.  One warp per row.
// =====================================================================
__global__ void __launch_bounds__(256) gat_s12(const float* __restrict__ a) {
    int row  = blockIdx.x * 8 + (threadIdx.x >> 5);
    int lane = threadIdx.x & 31;
    const float* wh = g_Wh + (size_t)row * 128;
    float p1 = 0.f, p2 = 0.f;
#pragma unroll
    for (int v = 0; v < 4; ++v) {
        int f = lane + v * 32;
        float w = wh[f];
        p1 += w * a[f];
        p2 += w * a[128 + f];
    }
#pragma unroll
    for (int o = 16; o; o >>= 1) {
        p1 += __shfl_xor_sync(0xffffffffu, p1, o);
        p2 += __shfl_xor_sync(0xffffffffu, p2, o);
    }
    if (lane == 0) { g_s1[row] = p1; g_s2[row] = p2; }
}

// =====================================================================
// Kernel 3 (main, fused): per block = (batch b, 32 rows of i).
// Preamble: row max of masked lrelu(s1_i + s2_j) = lrelu(s1_i + max masked s2_j).
// Loop over j in chunks of 32: stage Wh chunk + p-tile in smem, then
// register-blocked f32x2 GEMM: thread = 1 channel f x 32 rows (16 f32x2 accs).
// Row sums (softmax denominator) accumulated in registers, reduced once.
// =====================================================================
__global__ void __launch_bounds__(128) gat_main(const int* __restrict__ adj,
                                                float* __restrict__ out) {
    const int b    = blockIdx.y;
    const int i0   = blockIdx.x * 32;
    const int tid  = threadIdx.x;       // == fid, 0..127
    const int lane = tid & 31;
    const int wrp  = tid >> 5;

    __shared__ __align__(16) float wh_sm[32 * 128];  // [tj][f]
    __shared__ __align__(16) float p_sm[32 * 36];    // [tj][ti], stride 36
    __shared__ float s1_sm[32];
    __shared__ float rmax_sm[32];
    __shared__ float l_sm[32];

    const float* s2row = g_s2 + (size_t)b * NN;

    if (tid < 32) s1_sm[tid] = g_s1[(size_t)b * NN + i0 + tid];
    __syncthreads();

    // ---- preamble: masked row max (warp w handles rows w*8..w*8+7) ----
#pragma unroll
    for (int q = 0; q < 8; ++q) {
        int ti = wrp * 8 + q;
        const int* arow = adj + (size_t)(i0 + ti) * NN;
        float m = -3.0e38f;
        for (int j = lane; j < NN; j += 32)
            if (arow[j] > 0) m = fmaxf(m, s2row[j]);
#pragma unroll
        for (int o = 16; o; o >>= 1) m = fmaxf(m, __shfl_xor_sync(0xffffffffu, m, o));
        if (lane == 0) {
            float e = s1_sm[ti] + m;
            rmax_sm[ti] = e > 0.f ? e : 0.2f * e;
        }
    }

    unsigned long long acc[16];  // acc[u] = channels for ti = 2u, 2u+1
#pragma unroll
    for (int u = 0; u < 16; ++u) acc[u] = 0ull;
    float lloc[8];
#pragma unroll
    for (int q = 0; q < 8; ++q) lloc[q] = 0.f;

    const float* whbase = g_Wh + (size_t)b * NN * FF;

    for (int c = 0; c < NN / 32; ++c) {
        const int j0 = c * 32;
        __syncthreads();  // protects wh_sm/p_sm from previous chunk's readers

        // stage Wh[b, j0:j0+32, :] — contiguous 16 KB, coalesced float4
        {
            const float4* src = reinterpret_cast<const float4*>(whbase + (size_t)j0 * FF);
            float4* dst = reinterpret_cast<float4*>(wh_sm);
#pragma unroll
            for (int v = 0; v < 8; ++v) dst[tid + v * 128] = src[tid + v * 128];
        }

        // p-tile: thread computes 4 consecutive ti at tj = lane (x2 passes)
        float s2v = s2row[j0 + lane];
#pragma unroll
        for (int pass = 0; pass < 2; ++pass) {
            int ti0 = wrp * 4 + pass * 16;
            float pv[4];
#pragma unroll
            for (int q = 0; q < 4; ++q) {
                int ti = ti0 + q;
                int aij = adj[(size_t)(i0 + ti) * NN + j0 + lane];
                float e = s1_sm[ti] + s2v;
                e = e > 0.f ? e : 0.2f * e;
                float p = (aij > 0) ? __expf(e - rmax_sm[ti]) : 0.f;
                pv[q] = p;
                lloc[pass * 4 + q] += p;
            }
            *reinterpret_cast<float4*>(&p_sm[lane * 36 + ti0]) =
                make_float4(pv[0], pv[1], pv[2], pv[3]);
        }
        __syncthreads();

        // ---- register-blocked f32x2 GEMM: out[ti][f] += p[ti][tj]*wh[tj][f] ----
#pragma unroll 4
        for (int tj = 0; tj < 32; ++tj) {
            float wv = wh_sm[tj * 128 + tid];
            unsigned long long w2 = pack2(wv, wv);
            const ulonglong2* prow = reinterpret_cast<const ulonglong2*>(&p_sm[tj * 36]);
#pragma unroll
            for (int u = 0; u < 8; ++u) {
                ulonglong2 q = prow[u];                 // p[ti=4u..4u+3] as 2 pairs
                acc[2 * u]     = ffma2(q.x, w2, acc[2 * u]);
                acc[2 * u + 1] = ffma2(q.y, w2, acc[2 * u + 1]);
            }
        }
    }

    // ---- softmax denominators ----
#pragma unroll
    for (int q = 0; q < 8; ++q) {
        float v = lloc[q];
#pragma unroll
        for (int o = 16; o; o >>= 1) v += __shfl_xor_sync(0xffffffffu, v, o);
        if (lane == 0) l_sm[wrp * 4 + (q >> 2) * 16 + (q & 3)] = v;
    }
    __syncthreads();

    float* obase = out + ((size_t)b * NN + i0) * FF + tid;
#pragma unroll
    for (int u = 0; u < 16; ++u) {
        float x, y;
        unpack2(acc[u], x, y);
        obase[(size_t)(2 * u) * FF]     = x / l_sm[2 * u];
        obase[(size_t)(2 * u + 1) * FF] = y / l_sm[2 * u + 1];
    }
}

// =====================================================================
extern "C" void kernel_launch(void* const* d_in, const int* in_sizes, int n_in,
                              void* d_out, int out_size) {
    const float* h   = (const float*)d_in[0];
    const int*   adj = (const int*)d_in[1];
    const float* W   = (const float*)d_in[2];
    const float* a   = (const float*)d_in[3];
    float* out = (float*)d_out;

    gat_wh <<<(BB * NN) / 32, 256>>>(h, W);
    gat_s12<<<(BB * NN) / 8, 256>>>(a);
    dim3 grid(NN / 32, BB);
    gat_main<<<grid, 128>>>(adj, out);
}

// round 9
// speedup vs baseline: 1.6340x; 1.6340x over previous
#include <cuda_runtime.h>

#define BB 8
#define NN 2048
#define FF 128

// Scratch (no allocation allowed in kernel_launch)
__device__ float g_Wh[BB * NN * FF];   // 32 MB
__device__ float g_s1[BB * NN];
__device__ float g_s2[BB * NN];

// ---------- packed f32x2 helpers (FFMA2 — PTX-only on sm_103a) ----------
__device__ __forceinline__ unsigned long long pack2(float x, float y) {
    unsigned long long r;
    asm("mov.b64 %0, {%1, %2};" : "=l"(r) : "f"(x), "f"(y));
    return r;
}
__device__ __forceinline__ void unpack2(unsigned long long v, float& x, float& y) {
    asm("mov.b64 {%0, %1}, %2;" : "=f"(x), "=f"(y) : "l"(v));
}
__device__ __forceinline__ unsigned long long ffma2(unsigned long long a,
                                                    unsigned long long b,
                                                    unsigned long long c) {
    unsigned long long d;
    asm("fma.rn.f32x2 %0, %1, %2, %3;" : "=l"(d) : "l"(a), "l"(b), "l"(c));
    return d;
}

// =====================================================================
// Kernel 1: Wh = h @ W.   Block: 256 threads, 32 rows, K-tiled by 32.
// thread owns 4 f (float4 of W) x 4 rows -> 16 accumulators as 8 f32x2.
// =====================================================================
__global__ void __launch_bounds__(256) gat_wh(const float* __restrict__ h,
                                              const float* __restrict__ W) {
    const int row0 = blockIdx.x * 32;
    const int tid  = threadIdx.x;
    const int fgrp = tid & 31;   // f = fgrp*4 .. +3
    const int rgrp = tid >> 5;   // r = rgrp*4 .. +3

    __shared__ __align__(16) float W_sm[32 * 128];
    __shared__ float h_sm[32 * 32];

    unsigned long long acc[4][2];
#pragma unroll
    for (int r = 0; r < 4; ++r) { acc[r][0] = 0ull; acc[r][1] = 0ull; }

    for (int kt = 0; kt < 128; kt += 32) {
        __syncthreads();
        // W tile [32 k][128 f] — coalesced float4
        const float4* wsrc = reinterpret_cast<const float4*>(W + kt * 128);
        float4* wdst = reinterpret_cast<float4*>(W_sm);
#pragma unroll
        for (int v = 0; v < 4; ++v) wdst[tid + v * 256] = wsrc[tid + v * 256];
        // h tile [32 rows][32 k]
#pragma unroll
        for (int v = 0; v < 4; ++v) {
            int idx = tid + v * 256;
            int r = idx >> 5, kk = idx & 31;
            h_sm[idx] = h[(size_t)(row0 + r) * 128 + kt + kk];
        }
        __syncthreads();
#pragma unroll
        for (int kk = 0; kk < 32; ++kk) {
            ulonglong2 wq = *reinterpret_cast<const ulonglong2*>(&W_sm[kk * 128 + fgrp * 4]);
#pragma unroll
            for (int r = 0; r < 4; ++r) {
                float hv = h_sm[(rgrp * 4 + r) * 32 + kk];  // warp broadcast
                unsigned long long h2 = pack2(hv, hv);
                acc[r][0] = ffma2(h2, wq.x, acc[r][0]);
                acc[r][1] = ffma2(h2, wq.y, acc[r][1]);
            }
        }
    }
#pragma unroll
    for (int r = 0; r < 4; ++r) {
        float x0, x1, x2, x3;
        unpack2(acc[r][0], x0, x1);
        unpack2(acc[r][1], x2, x3);
        *reinterpret_cast<float4*>(&g_Wh[(size_t)(row0 + rgrp * 4 + r) * 128 + fgrp * 4]) =
            make_float4(x0, x1, x2, x3);
    }
}

// =====================================================================
// Kernel 2: s1 = Wh @ a1, s2 = Wh @ a2.  One warp per row.
// =====================================================================
__global__ void __launch_bounds__(256) gat_s12(const float* __restrict__ a) {
    int row  = blockIdx.x * 8 + (threadIdx.x >> 5);
    int lane = threadIdx.x & 31;
    const float* wh = g_Wh + (size_t)row * 128;
    float p1 = 0.f, p2 = 0.f;
#pragma unroll
    for (int v = 0; v < 4; ++v) {
        int f = lane + v * 32;
        float w = wh[f];
        p1 += w * a[f];
        p2 += w * a[128 + f];
    }
#pragma unroll
    for (int o = 16; o; o >>= 1) {
        p1 += __shfl_xor_sync(0xffffffffu, p1, o);
        p2 += __shfl_xor_sync(0xffffffffu, p2, o);
    }
    if (lane == 0) { g_s1[row] = p1; g_s2[row] = p2; }
}

// =====================================================================
// Kernel 3 (main, fused): per block = (batch b, 32 rows of i).
// Preamble: row max of masked lrelu(s1_i + s2_j) = lrelu(s1_i + max masked s2_j).
// Loop over j in chunks of 32: stage Wh chunk + p-tile in smem, then
// register-blocked f32x2 GEMM: thread = 1 channel f x 32 rows (16 f32x2 accs).
// Row sums (softmax denominator) accumulated in registers, reduced once.
// =====================================================================
__global__ void __launch_bounds__(128) gat_main(const int* __restrict__ adj,
                                                float* __restrict__ out) {
    const int b    = blockIdx.y;
    const int i0   = blockIdx.x * 32;
    const int tid  = threadIdx.x;       // == fid, 0..127
    const int lane = tid & 31;
    const int wrp  = tid >> 5;

    __shared__ __align__(16) float wh_sm[32 * 128];  // [tj][f]
    __shared__ __align__(16) float p_sm[32 * 36];    // [tj][ti], stride 36
    __shared__ float s1_sm[32];
    __shared__ float rmax_sm[32];
    __shared__ float l_sm[32];

    const float* s2row = g_s2 + (size_t)b * NN;

    if (tid < 32) s1_sm[tid] = g_s1[(size_t)b * NN + i0 + tid];
    __syncthreads();

    // ---- preamble: masked row max (warp w handles rows w*8..w*8+7) ----
#pragma unroll
    for (int q = 0; q < 8; ++q) {
        int ti = wrp * 8 + q;
        const int* arow = adj + (size_t)(i0 + ti) * NN;
        float m = -3.0e38f;
        for (int j = lane; j < NN; j += 32)
            if (arow[j] > 0) m = fmaxf(m, s2row[j]);
#pragma unroll
        for (int o = 16; o; o >>= 1) m = fmaxf(m, __shfl_xor_sync(0xffffffffu, m, o));
        if (lane == 0) {
            float e = s1_sm[ti] + m;
            rmax_sm[ti] = e > 0.f ? e : 0.2f * e;
        }
    }

    unsigned long long acc[16];  // acc[u] = channels for ti = 2u, 2u+1
#pragma unroll
    for (int u = 0; u < 16; ++u) acc[u] = 0ull;
    float lloc[8];
#pragma unroll
    for (int q = 0; q < 8; ++q) lloc[q] = 0.f;

    const float* whbase = g_Wh + (size_t)b * NN * FF;

    for (int c = 0; c < NN / 32; ++c) {
        const int j0 = c * 32;
        __syncthreads();  // protects wh_sm/p_sm from previous chunk's readers

        // stage Wh[b, j0:j0+32, :] — contiguous 16 KB, coalesced float4
        {
            const float4* src = reinterpret_cast<const float4*>(whbase + (size_t)j0 * FF);
            float4* dst = reinterpret_cast<float4*>(wh_sm);
#pragma unroll
            for (int v = 0; v < 8; ++v) dst[tid + v * 128] = src[tid + v * 128];
        }

        // p-tile: thread computes 4 consecutive ti at tj = lane (x2 passes)
        float s2v = s2row[j0 + lane];
#pragma unroll
        for (int pass = 0; pass < 2; ++pass) {
            int ti0 = wrp * 4 + pass * 16;
            float pv[4];
#pragma unroll
            for (int q = 0; q < 4; ++q) {
                int ti = ti0 + q;
                int aij = adj[(size_t)(i0 + ti) * NN + j0 + lane];
                float e = s1_sm[ti] + s2v;
                e = e > 0.f ? e : 0.2f * e;
                float p = (aij > 0) ? __expf(e - rmax_sm[ti]) : 0.f;
                pv[q] = p;
                lloc[pass * 4 + q] += p;
            }
            *reinterpret_cast<float4*>(&p_sm[lane * 36 + ti0]) =
                make_float4(pv[0], pv[1], pv[2], pv[3]);
        }
        __syncthreads();

        // ---- register-blocked f32x2 GEMM: out[ti][f] += p[ti][tj]*wh[tj][f] ----
#pragma unroll 4
        for (int tj = 0; tj < 32; ++tj) {
            float wv = wh_sm[tj * 128 + tid];
            unsigned long long w2 = pack2(wv, wv);
            const ulonglong2* prow = reinterpret_cast<const ulonglong2*>(&p_sm[tj * 36]);
#pragma unroll
            for (int u = 0; u < 8; ++u) {
                ulonglong2 q = prow[u];                 // p[ti=4u..4u+3] as 2 pairs
                acc[2 * u]     = ffma2(q.x, w2, acc[2 * u]);
                acc[2 * u + 1] = ffma2(q.y, w2, acc[2 * u + 1]);
            }
        }
    }

    // ---- softmax denominators ----
#pragma unroll
    for (int q = 0; q < 8; ++q) {
        float v = lloc[q];
#pragma unroll
        for (int o = 16; o; o >>= 1) v += __shfl_xor_sync(0xffffffffu, v, o);
        if (lane == 0) l_sm[wrp * 4 + (q >> 2) * 16 + (q & 3)] = v;
    }
    __syncthreads();

    float* obase = out + ((size_t)b * NN + i0) * FF + tid;
#pragma unroll
    for (int u = 0; u < 16; ++u) {
        float x, y;
        unpack2(acc[u], x, y);
        obase[(size_t)(2 * u) * FF]     = x / l_sm[2 * u];
        obase[(size_t)(2 * u + 1) * FF] = y / l_sm[2 * u + 1];
    }
}

// =====================================================================
extern "C" void kernel_launch(void* const* d_in, const int* in_sizes, int n_in,
                              void* d_out, int out_size) {
    const float* h   = (const float*)d_in[0];
    const int*   adj = (const int*)d_in[1];
    const float* W   = (const float*)d_in[2];
    const float* a   = (const float*)d_in[3];
    float* out = (float*)d_out;

    gat_wh <<<(BB * NN) / 32, 256>>>(h, W);
    gat_s12<<<(BB * NN) / 8, 256>>>(a);
    dim3 grid(NN / 32, BB);
    gat_main<<<grid, 128>>>(adj, out);
}

// round 10
// speedup vs baseline: 1.6364x; 1.0014x over previous
#include <cuda_runtime.h>

#define BB 8
#define NN 2048
#define FF 128

// Scratch (no allocation allowed in kernel_launch)
__device__ float g_Wh[BB * NN * FF];   // 32 MB
__device__ float g_s1[BB * NN];
__device__ float g_s2[BB * NN];

// ---------- packed f32x2 helpers (FFMA2 — PTX-only on sm_103a) ----------
__device__ __forceinline__ unsigned long long pack2(float x, float y) {
    unsigned long long r;
    asm("mov.b64 %0, {%1, %2};" : "=l"(r) : "f"(x), "f"(y));
    return r;
}
__device__ __forceinline__ void unpack2(unsigned long long v, float& x, float& y) {
    asm("mov.b64 {%0, %1}, %2;" : "=f"(x), "=f"(y) : "l"(v));
}
__device__ __forceinline__ unsigned long long ffma2(unsigned long long a,
                                                    unsigned long long b,
                                                    unsigned long long c) {
    unsigned long long d;
    asm("fma.rn.f32x2 %0, %1, %2, %3;" : "=l"(d) : "l"(a), "l"(b), "l"(c));
    return d;
}

// =====================================================================
// Kernel 1: Wh = h @ W.   Block: 256 threads, 32 rows, K-tiled by 32.
// thread owns 4 f (float4 of W) x 4 rows -> 16 accumulators as 8 f32x2.
// =====================================================================
__global__ void __launch_bounds__(256) gat_wh(const float* __restrict__ h,
                                              const float* __restrict__ W) {
    const int row0 = blockIdx.x * 32;
    const int tid  = threadIdx.x;
    const int fgrp = tid & 31;   // f = fgrp*4 .. +3
    const int rgrp = tid >> 5;   // r = rgrp*4 .. +3

    __shared__ __align__(16) float W_sm[32 * 128];
    __shared__ float h_sm[32 * 32];

    unsigned long long acc[4][2];
#pragma unroll
    for (int r = 0; r < 4; ++r) { acc[r][0] = 0ull; acc[r][1] = 0ull; }

    for (int kt = 0; kt < 128; kt += 32) {
        __syncthreads();
        // W tile [32 k][128 f] — coalesced float4
        const float4* wsrc = reinterpret_cast<const float4*>(W + kt * 128);
        float4* wdst = reinterpret_cast<float4*>(W_sm);
#pragma unroll
        for (int v = 0; v < 4; ++v) wdst[tid + v * 256] = wsrc[tid + v * 256];
        // h tile [32 rows][32 k]
#pragma unroll
        for (int v = 0; v < 4; ++v) {
            int idx = tid + v * 256;
            int r = idx >> 5, kk = idx & 31;
            h_sm[idx] = h[(size_t)(row0 + r) * 128 + kt + kk];
        }
        __syncthreads();
#pragma unroll
        for (int kk = 0; kk < 32; ++kk) {
            ulonglong2 wq = *reinterpret_cast<const ulonglong2*>(&W_sm[kk * 128 + fgrp * 4]);
#pragma unroll
            for (int r = 0; r < 4; ++r) {
                float hv = h_sm[(rgrp * 4 + r) * 32 + kk];  // warp broadcast
                unsigned long long h2 = pack2(hv, hv);
                acc[r][0] = ffma2(h2, wq.x, acc[r][0]);
                acc[r][1] = ffma2(h2, wq.y, acc[r][1]);
            }
        }
    }
#pragma unroll
    for (int r = 0; r < 4; ++r) {
        float x0, x1, x2, x3;
        unpack2(acc[r][0], x0, x1);
        unpack2(acc[r][1], x2, x3);
        *reinterpret_cast<float4*>(&g_Wh[(size_t)(row0 + rgrp * 4 + r) * 128 + fgrp * 4]) =
            make_float4(x0, x1, x2, x3);
    }
}

// =====================================================================
// Kernel 2: s1 = Wh @ a1, s2 = Wh @ a2.  One warp per row.
// =====================================================================
__global__ void __launch_bounds__(256) gat_s12(const float* __restrict__ a) {
    int row  = blockIdx.x * 8 + (threadIdx.x >> 5);
    int lane = threadIdx.x & 31;
    const float* wh = g_Wh + (size_t)row * 128;
    float p1 = 0.f, p2 = 0.f;
#pragma unroll
    for (int v = 0; v < 4; ++v) {
        int f = lane + v * 32;
        float w = wh[f];
        p1 += w * a[f];
        p2 += w * a[128 + f];
    }
#pragma unroll
    for (int o = 16; o; o >>= 1) {
        p1 += __shfl_xor_sync(0xffffffffu, p1, o);
        p2 += __shfl_xor_sync(0xffffffffu, p2, o);
    }
    if (lane == 0) { g_s1[row] = p1; g_s2[row] = p2; }
}

// =====================================================================
// Kernel 3 (main, fused): per block = (batch b, 32 rows of i).
// Preamble: row max of masked lrelu(s1_i + s2_j) = lrelu(s1_i + max masked s2_j).
// Loop over j in chunks of 32: stage Wh chunk + p-tile in smem, then
// register-blocked f32x2 GEMM: thread = 1 channel f x 32 rows (16 f32x2 accs).
// Row sums (softmax denominator) accumulated in registers, reduced once.
// =====================================================================
__global__ void __launch_bounds__(128) gat_main(const int* __restrict__ adj,
                                                float* __restrict__ out) {
    const int b    = blockIdx.y;
    const int i0   = blockIdx.x * 32;
    const int tid  = threadIdx.x;       // == fid, 0..127
    const int lane = tid & 31;
    const int wrp  = tid >> 5;

    __shared__ __align__(16) float wh_sm[32 * 128];  // [tj][f]
    __shared__ __align__(16) float p_sm[32 * 36];    // [tj][ti], stride 36
    __shared__ float s1_sm[32];
    __shared__ float rmax_sm[32];
    __shared__ float l_sm[32];

    const float* s2row = g_s2 + (size_t)b * NN;

    if (tid < 32) s1_sm[tid] = g_s1[(size_t)b * NN + i0 + tid];
    __syncthreads();

    // ---- preamble: masked row max (warp w handles rows w*8..w*8+7) ----
#pragma unroll
    for (int q = 0; q < 8; ++q) {
        int ti = wrp * 8 + q;
        const int* arow = adj + (size_t)(i0 + ti) * NN;
        float m = -3.0e38f;
        for (int j = lane; j < NN; j += 32)
            if (arow[j] > 0) m = fmaxf(m, s2row[j]);
#pragma unroll
        for (int o = 16; o; o >>= 1) m = fmaxf(m, __shfl_xor_sync(0xffffffffu, m, o));
        if (lane == 0) {
            float e = s1_sm[ti] + m;
            rmax_sm[ti] = e > 0.f ? e : 0.2f * e;
        }
    }

    unsigned long long acc[16];  // acc[u] = channels for ti = 2u, 2u+1
#pragma unroll
    for (int u = 0; u < 16; ++u) acc[u] = 0ull;
    float lloc[8];
#pragma unroll
    for (int q = 0; q < 8; ++q) lloc[q] = 0.f;

    const float* whbase = g_Wh + (size_t)b * NN * FF;

    for (int c = 0; c < NN / 32; ++c) {
        const int j0 = c * 32;
        __syncthreads();  // protects wh_sm/p_sm from previous chunk's readers

        // stage Wh[b, j0:j0+32, :] — contiguous 16 KB, coalesced float4
        {
            const float4* src = reinterpret_cast<const float4*>(whbase + (size_t)j0 * FF);
            float4* dst = reinterpret_cast<float4*>(wh_sm);
#pragma unroll
            for (int v = 0; v < 8; ++v) dst[tid + v * 128] = src[tid + v * 128];
        }

        // p-tile: thread computes 4 consecutive ti at tj = lane (x2 passes)
        float s2v = s2row[j0 + lane];
#pragma unroll
        for (int pass = 0; pass < 2; ++pass) {
            int ti0 = wrp * 4 + pass * 16;
            float pv[4];
#pragma unroll
            for (int q = 0; q < 4; ++q) {
                int ti = ti0 + q;
                int aij = adj[(size_t)(i0 + ti) * NN + j0 + lane];
                float e = s1_sm[ti] + s2v;
                e = e > 0.f ? e : 0.2f * e;
                float p = (aij > 0) ? __expf(e - rmax_sm[ti]) : 0.f;
                pv[q] = p;
                lloc[pass * 4 + q] += p;
            }
            *reinterpret_cast<float4*>(&p_sm[lane * 36 + ti0]) =
                make_float4(pv[0], pv[1], pv[2], pv[3]);
        }
        __syncthreads();

        // ---- register-blocked f32x2 GEMM: out[ti][f] += p[ti][tj]*wh[tj][f] ----
#pragma unroll 4
        for (int tj = 0; tj < 32; ++tj) {
            float wv = wh_sm[tj * 128 + tid];
            unsigned long long w2 = pack2(wv, wv);
            const ulonglong2* prow = reinterpret_cast<const ulonglong2*>(&p_sm[tj * 36]);
#pragma unroll
            for (int u = 0; u < 8; ++u) {
                ulonglong2 q = prow[u];                 // p[ti=4u..4u+3] as 2 pairs
                acc[2 * u]     = ffma2(q.x, w2, acc[2 * u]);
                acc[2 * u + 1] = ffma2(q.y, w2, acc[2 * u + 1]);
            }
        }
    }

    // ---- softmax denominators ----
#pragma unroll
    for (int q = 0; q < 8; ++q) {
        float v = lloc[q];
#pragma unroll
        for (int o = 16; o; o >>= 1) v += __shfl_xor_sync(0xffffffffu, v, o);
        if (lane == 0) l_sm[wrp * 4 + (q >> 2) * 16 + (q & 3)] = v;
    }
    __syncthreads();

    float* obase = out + ((size_t)b * NN + i0) * FF + tid;
#pragma unroll
    for (int u = 0; u < 16; ++u) {
        float x, y;
        unpack2(acc[u], x, y);
        obase[(size_t)(2 * u) * FF]     = x / l_sm[2 * u];
        obase[(size_t)(2 * u + 1) * FF] = y / l_sm[2 * u + 1];
    }
}

// =====================================================================
extern "C" void kernel_launch(void* const* d_in, const int* in_sizes, int n_in,
                              void* d_out, int out_size) {
    const float* h   = (const float*)d_in[0];
    const int*   adj = (const int*)d_in[1];
    const float* W   = (const float*)d_in[2];
    const float* a   = (const float*)d_in[3];
    float* out = (float*)d_out;

    gat_wh <<<(BB * NN) / 32, 256>>>(h, W);
    gat_s12<<<(BB * NN) / 8, 256>>>(a);
    dim3 grid(NN / 32, BB);
    gat_main<<<grid, 128>>>(adj, out);
}

// round 11
// speedup vs baseline: 1.7857x; 1.0913x over previous
#include <cuda_runtime.h>
#include <cstdint>

#define BB 8
#define NN 2048
#define FF 128
#define NC (NN / 32)

// Scratch (no allocation allowed in kernel_launch)
__device__ float g_Wh[BB * NN * FF];
__device__ float g_s1[BB * NN];
__device__ float g_s2[BB * NN];
__device__ float g_A[BB * NN];
__device__ float g_B[BB * NN];
__device__ float g_C[BB * NN];
__device__ float g_D[BB * NN];
__device__ float g_Ms2[BB];

// ---------- packed f32x2 helpers (FFMA2 — PTX-only on sm_103a) ----------
__device__ __forceinline__ unsigned long long pack2(float x, float y) {
    unsigned long long r;
    asm("mov.b64 %0, {%1, %2};" : "=l"(r) : "f"(x), "f"(y));
    return r;
}
__device__ __forceinline__ void unpack2(unsigned long long v, float& x, float& y) {
    asm("mov.b64 {%0, %1}, %2;" : "=f"(x), "=f"(y) : "l"(v));
}
__device__ __forceinline__ unsigned long long ffma2(unsigned long long a,
                                                    unsigned long long b,
                                                    unsigned long long c) {
    unsigned long long d;
    asm("fma.rn.f32x2 %0, %1, %2, %3;" : "=l"(d) : "l"(a), "l"(b), "l"(c));
    return d;
}

// ---------- cp.async helpers ----------
__device__ __forceinline__ void cp_async16(uint32_t dst_smem, const void* src) {
    asm volatile("cp.async.cg.shared.global [%0], [%1], 16;\n" ::"r"(dst_smem), "l"(src));
}
__device__ __forceinline__ void cp_commit() {
    asm volatile("cp.async.commit_group;\n");
}

// =====================================================================
// Kernel 1: Wh = h @ W (unchanged — 22us, not the bottleneck)
// =====================================================================
__global__ void __launch_bounds__(256) gat_wh(const float* __restrict__ h,
                                              const float* __restrict__ W) {
    const int row0 = blockIdx.x * 32;
    const int tid  = threadIdx.x;
    const int fgrp = tid & 31;
    const int rgrp = tid >> 5;

    __shared__ __align__(16) float W_sm[32 * 128];
    __shared__ float h_sm[32 * 32];

    unsigned long long acc[4][2];
#pragma unroll
    for (int r = 0; r < 4; ++r) { acc[r][0] = 0ull; acc[r][1] = 0ull; }

    for (int kt = 0; kt < 128; kt += 32) {
        __syncthreads();
        const float4* wsrc = reinterpret_cast<const float4*>(W + kt * 128);
        float4* wdst = reinterpret_cast<float4*>(W_sm);
#pragma unroll
        for (int v = 0; v < 4; ++v) wdst[tid + v * 256] = wsrc[tid + v * 256];
#pragma unroll
        for (int v = 0; v < 4; ++v) {
            int idx = tid + v * 256;
            int r = idx >> 5, kk = idx & 31;
            h_sm[idx] = h[(size_t)(row0 + r) * 128 + kt + kk];
        }
        __syncthreads();
#pragma unroll
        for (int kk = 0; kk < 32; ++kk) {
            ulonglong2 wq = *reinterpret_cast<const ulonglong2*>(&W_sm[kk * 128 + fgrp * 4]);
#pragma unroll
            for (int r = 0; r < 4; ++r) {
                float hv = h_sm[(rgrp * 4 + r) * 32 + kk];
                unsigned long long h2 = pack2(hv, hv);
                acc[r][0] = ffma2(h2, wq.x, acc[r][0]);
                acc[r][1] = ffma2(h2, wq.y, acc[r][1]);
            }
        }
    }
#pragma unroll
    for (int r = 0; r < 4; ++r) {
        float x0, x1, x2, x3;
        unpack2(acc[r][0], x0, x1);
        unpack2(acc[r][1], x2, x3);
        *reinterpret_cast<float4*>(&g_Wh[(size_t)(row0 + rgrp * 4 + r) * 128 + fgrp * 4]) =
            make_float4(x0, x1, x2, x3);
    }
}

// =====================================================================
// Kernel 2: s1 = Wh @ a1, s2 = Wh @ a2.
// =====================================================================
__global__ void __launch_bounds__(256) gat_s12(const float* __restrict__ a) {
    int row  = blockIdx.x * 8 + (threadIdx.x >> 5);
    int lane = threadIdx.x & 31;
    const float* wh = g_Wh + (size_t)row * 128;
    float p1 = 0.f, p2 = 0.f;
#pragma unroll
    for (int v = 0; v < 4; ++v) {
        int f = lane + v * 32;
        float w = wh[f];
        p1 += w * a[f];
        p2 += w * a[128 + f];
    }
#pragma unroll
    for (int o = 16; o; o >>= 1) {
        p1 += __shfl_xor_sync(0xffffffffu, p1, o);
        p2 += __shfl_xor_sync(0xffffffffu, p2, o);
    }
    if (lane == 0) { g_s1[row] = p1; g_s2[row] = p2; }
}

// =====================================================================
// Kernel 2b: Ms2[b] = max_j s2[b, j]  (unmasked global max — any M >= rowmax
// leaves softmax exactly invariant; s-values are O(8) so no underflow risk)
// =====================================================================
__global__ void __launch_bounds__(256) gat_max() {
    int b = blockIdx.x;
    const float* s2 = g_s2 + (size_t)b * NN;
    float m = -3.0e38f;
    for (int j = threadIdx.x; j < NN; j += 256) m = fmaxf(m, s2[j]);
    __shared__ float red[8];
#pragma unroll
    for (int o = 16; o; o >>= 1) m = fmaxf(m, __shfl_xor_sync(0xffffffffu, m, o));
    if ((threadIdx.x & 31) == 0) red[threadIdx.x >> 5] = m;
    __syncthreads();
    if (threadIdx.x == 0) {
        float r = red[0];
#pragma unroll
        for (int k = 1; k < 8; ++k) r = fmaxf(r, red[k]);
        g_Ms2[b] = r;
    }
}

// =====================================================================
// Kernel 2c: exponential factor tables.
//   M_i = lrelu(s1_i + Ms2)    (>= per-row masked max since lrelu monotone)
//   A = exp(s1 - M), B = exp(0.2 s1 - M), C = exp(s2), D = exp(0.2 s2)
//   p_ij = adj ? ( (s1+s2>0) ? A_i*C_j : B_i*D_j ) : 0   — all products <= 1.
// =====================================================================
__global__ void __launch_bounds__(256) gat_abcd() {
    int i = blockIdx.x * 256 + threadIdx.x;
    int b = i / NN;
    float s1 = g_s1[i], s2 = g_s2[i], Ms2 = g_Ms2[b];
    float t = s1 + Ms2;
    float M = t > 0.f ? t : 0.2f * t;
    g_A[i] = expf(s1 - M);
    g_B[i] = expf(0.2f * s1 - M);
    g_C[i] = expf(s2);
    g_D[i] = expf(0.2f * s2);
}

// =====================================================================
// Kernel 3 (main): block = (b, 32 rows of i), 128 threads (thread = channel f).
//  - Wh chunks double-buffered via cp.async (latency hidden under GEMM)
//  - p-tile inputs (adj/s2/C/D) prefetched to regs one chunk ahead
//  - no exp / no adj pre-scan in the hot loop
// =====================================================================
__global__ void __launch_bounds__(128) gat_main(const int* __restrict__ adj,
                                                float* __restrict__ out) {
    const int b    = blockIdx.y;
    const int i0   = blockIdx.x * 32;
    const int tid  = threadIdx.x;
    const int lane = tid & 31;
    const int wrp  = tid >> 5;

    __shared__ __align__(16) float wh_sm[2][32 * 128];   // 32 KB
    __shared__ __align__(16) float p_sm[2][32 * 36];     // 9.2 KB
    __shared__ float s1_sm[32], A_sm[32], B_sm[32], l_sm[32];

    if (tid < 32) {
        size_t g = (size_t)b * NN + i0 + tid;
        s1_sm[tid] = g_s1[g];
        A_sm[tid]  = g_A[g];
        B_sm[tid]  = g_B[g];
    }

    const float* s2row  = g_s2 + (size_t)b * NN;
    const float* Crow   = g_C + (size_t)b * NN;
    const float* Drow   = g_D + (size_t)b * NN;
    const float* whbase = g_Wh + (size_t)b * NN * FF;

    const uint32_t wh_dst0 = (uint32_t)__cvta_generic_to_shared(&wh_sm[0][0]);
    const uint32_t wh_dst1 = (uint32_t)__cvta_generic_to_shared(&wh_sm[1][0]);

    // ---- prefetch regs for chunk 0 ----
    int   adjc[8];
    float s2v, Cv, Dv;
    {
        int j = lane;
        s2v = s2row[j]; Cv = Crow[j]; Dv = Drow[j];
#pragma unroll
        for (int idx = 0; idx < 8; ++idx) {
            int ti = wrp * 4 + (idx >> 2) * 16 + (idx & 3);
            adjc[idx] = adj[(size_t)(i0 + ti) * NN + j];
        }
    }
    // ---- stage chunk 0 ----
    {
        const float* src = whbase;
#pragma unroll
        for (int v = 0; v < 8; ++v)
            cp_async16(wh_dst0 + (uint32_t)(tid + v * 128) * 16, src + (tid + v * 128) * 4);
        cp_commit();
    }

    unsigned long long acc[16];
#pragma unroll
    for (int u = 0; u < 16; ++u) acc[u] = 0ull;
    float lloc[8];
#pragma unroll
    for (int q = 0; q < 8; ++q) lloc[q] = 0.f;

    for (int c = 0; c < NC; ++c) {
        __syncthreads();  // prior iteration's reads of the buffers we touch next are done

        // stage chunk c+1 into the other wh buffer
        if (c + 1 < NC) {
            uint32_t dst = ((c + 1) & 1) ? wh_dst1 : wh_dst0;
            const float* src = whbase + (size_t)(c + 1) * 32 * FF;
#pragma unroll
            for (int v = 0; v < 8; ++v)
                cp_async16(dst + (uint32_t)(tid + v * 128) * 16, src + (tid + v * 128) * 4);
            cp_commit();
        }

        // ---- p-tile for chunk c (from prefetched regs; no exp, no extra LDG) ----
        float* pbuf = p_sm[c & 1];
#pragma unroll
        for (int pass = 0; pass < 2; ++pass) {
            const int ti0 = wrp * 4 + pass * 16;
            float pv[4];
#pragma unroll
            for (int q = 0; q < 4; ++q) {
                int ti  = ti0 + q;
                int idx = pass * 4 + q;
                float u = s1_sm[ti] + s2v;
                bool gpos = u > 0.f;
                float x = gpos ? A_sm[ti] : B_sm[ti];
                float y = gpos ? Cv : Dv;
                float p = (adjc[idx] > 0) ? x * y : 0.f;
                pv[q] = p;
                lloc[idx] += p;
            }
            *reinterpret_cast<float4*>(&pbuf[lane * 36 + ti0]) =
                make_float4(pv[0], pv[1], pv[2], pv[3]);
        }

        // ---- prefetch chunk c+1 p-inputs (lands during this chunk's GEMM) ----
        if (c + 1 < NC) {
            int j = (c + 1) * 32 + lane;
            s2v = s2row[j]; Cv = Crow[j]; Dv = Drow[j];
#pragma unroll
            for (int idx = 0; idx < 8; ++idx) {
                int ti = wrp * 4 + (idx >> 2) * 16 + (idx & 3);
                adjc[idx] = adj[(size_t)(i0 + ti) * NN + j];
            }
            asm volatile("cp.async.wait_group 1;\n");  // chunk c arrived
        } else {
            asm volatile("cp.async.wait_group 0;\n");
        }
        __syncthreads();  // cp.async data + p_sm visible to all

        // ---- register-blocked f32x2 GEMM on chunk c ----
        const float* whb = wh_sm[c & 1];
        const float* pb  = p_sm[c & 1];
#pragma unroll 4
        for (int tj = 0; tj < 32; ++tj) {
            float wv = whb[tj * 128 + tid];
            unsigned long long w2 = pack2(wv, wv);
            const ulonglong2* prow = reinterpret_cast<const ulonglong2*>(&pb[tj * 36]);
#pragma unroll
            for (int u = 0; u < 8; ++u) {
                ulonglong2 q = prow[u];
                acc[2 * u]     = ffma2(q.x, w2, acc[2 * u]);
                acc[2 * u + 1] = ffma2(q.y, w2, acc[2 * u + 1]);
            }
        }
    }

    // ---- softmax denominators ----
#pragma unroll
    for (int q = 0; q < 8; ++q) {
        float v = lloc[q];
#pragma unroll
        for (int o = 16; o; o >>= 1) v += __shfl_xor_sync(0xffffffffu, v, o);
        if (lane == 0) l_sm[wrp * 4 + (q >> 2) * 16 + (q & 3)] = v;
    }
    __syncthreads();

    float* obase = out + ((size_t)b * NN + i0) * FF + tid;
#pragma unroll
    for (int u = 0; u < 16; ++u) {
        float x, y;
        unpack2(acc[u], x, y);
        obase[(size_t)(2 * u) * FF]     = x / l_sm[2 * u];
        obase[(size_t)(2 * u + 1) * FF] = y / l_sm[2 * u + 1];
    }
}

// =====================================================================
extern "C" void kernel_launch(void* const* d_in, const int* in_sizes, int n_in,
                              void* d_out, int out_size) {
    const float* h   = (const float*)d_in[0];
    const int*   adj = (const int*)d_in[1];
    const float* W   = (const float*)d_in[2];
    const float* a   = (const float*)d_in[3];
    float* out = (float*)d_out;

    gat_wh  <<<(BB * NN) / 32, 256>>>(h, W);
    gat_s12 <<<(BB * NN) / 8, 256>>>(a);
    gat_max <<<BB, 256>>>();
    gat_abcd<<<(BB * NN) / 256, 256>>>();
    dim3 grid(NN / 32, BB);
    gat_main<<<grid, 128>>>(adj, out);
}